// round 12
// baseline (speedup 1.0000x reference)
#include <cuda_runtime.h>
#include <cuda_bf16.h>
#include <cstdint>
#include <cstddef>

// Problem constants
#define T_STEPS 100
#define B_DIM   512
#define I_DIM   512
#define O_DIM   512
#define M_DIM   (T_STEPS * B_DIM)   // 51200
#define BO      (B_DIM * O_DIM)     // 262144

#define BETA_F   0.9f
#define THRESH_F 1.0f
#define DELTA_MEM 1.5e-4f           // flag margin: ~3.5x max |mem_tc - mem_seq|

// Scratch for input currents cur[T, B, O] (105 MB)
__device__ float g_cur[(size_t)T_STEPS * B_DIM * O_DIM];
// Flag worklist of ambiguous neurons (bo indices)
__device__ int g_flag_list[BO];
__device__ int g_flag_cnt;

// ---------------------------------------------------------------------------
// bf16x2 split GEMM on legacy tensor cores — R10 structure (measured 343us):
// all 8 warps interleave split/store and mma; double-buffered smem; gmem
// prefetch of chunk k+1 issued before the mma block of chunk k.
// 3 product GEMMs: (a1,b1), (a1,b2), (a2,b1); dropped term ~2^-18 rel.
// ---------------------------------------------------------------------------
#define KC        64
#define NKC       (I_DIM / KC)        // 8
#define TILE_B    (128 * 128)         // 16384 B: 128 rows x 64 bf16 (128B rows)
#define BUF_B     (4 * TILE_B)        // 65536 B: a1 a2 b1 b2
#define SMEM_ASK  (1024 + 2 * BUF_B)  // 132096 B

static __device__ __forceinline__ uint32_t smem_u32(const void* p) {
    uint32_t a;
    asm("{ .reg .u64 t; cvta.to.shared.u64 t, %1; cvt.u32.u64 %0, t; }"
        : "=r"(a) : "l"(p));
    return a;
}

#define LDSM4(r0, r1, r2, r3, addr) \
    asm volatile("ldmatrix.sync.aligned.m8n8.x4.shared.b16 {%0,%1,%2,%3}, [%4];" \
        : "=r"(r0), "=r"(r1), "=r"(r2), "=r"(r3) : "r"(addr))

#define MMA_OP(D, A, b0, b1) \
    asm volatile("mma.sync.aligned.m16n8k16.row.col.f32.bf16.bf16.f32 " \
        "{%0,%1,%2,%3}, {%4,%5,%6,%7}, {%8,%9}, {%0,%1,%2,%3};" \
        : "+f"((D)[0]), "+f"((D)[1]), "+f"((D)[2]), "+f"((D)[3]) \
        : "r"((A)[0]), "r"((A)[1]), "r"((A)[2]), "r"((A)[3]), "r"(b0), "r"(b1))

static __device__ __forceinline__ uint32_t pack2(__nv_bfloat16 lo, __nv_bfloat16 hi) {
    __nv_bfloat162 p = __halves2bfloat162(lo, hi);
    return *reinterpret_cast<uint32_t*>(&p);
}

static __device__ __forceinline__ void split_store2(char* tile0, uint32_t sw, float4 v) {
    float f0 = v.x, f1 = v.y, f2 = v.z, f3 = v.w;

    __nv_bfloat16 a0 = __float2bfloat16_rn(f0);
    __nv_bfloat16 a1 = __float2bfloat16_rn(f1);
    __nv_bfloat16 a2 = __float2bfloat16_rn(f2);
    __nv_bfloat16 a3 = __float2bfloat16_rn(f3);

    float r0 = f0 - __bfloat162float(a0);
    float r1 = f1 - __bfloat162float(a1);
    float r2 = f2 - __bfloat162float(a2);
    float r3 = f3 - __bfloat162float(a3);

    __nv_bfloat16 b0 = __float2bfloat16_rn(r0);
    __nv_bfloat16 b1 = __float2bfloat16_rn(r1);
    __nv_bfloat16 b2 = __float2bfloat16_rn(r2);
    __nv_bfloat16 b3 = __float2bfloat16_rn(r3);

    uint2 w1; w1.x = pack2(a0, a1); w1.y = pack2(a2, a3);
    uint2 w2; w2.x = pack2(b0, b1); w2.y = pack2(b2, b3);

    *reinterpret_cast<uint2*>(tile0 + sw)          = w1;
    *reinterpret_cast<uint2*>(tile0 + TILE_B + sw) = w2;
}

__global__ void __launch_bounds__(256)
snn_gemm_mma(const float* __restrict__ X, const float* __restrict__ Wm,
             const float* __restrict__ bias)
{
    extern __shared__ char smraw[];
    char* sm = (char*)((((uintptr_t)smraw) + 1023) & ~(uintptr_t)1023);
    const uint32_t sb = smem_u32(sm);

    const int tid  = threadIdx.x;
    const int warp = tid >> 5;
    const int lane = tid & 31;
    const int wm   = warp & 3;
    const int wn   = warp >> 2;

    const int n0 = blockIdx.x * 128;
    const int m0 = blockIdx.y * 128;

    const float* xs0 = X  + (size_t)m0 * I_DIM;
    const float* ws0 = Wm + (size_t)n0 * I_DIM;

    float acc[2][8][4] = {};
    float4 px[8], pw[8];

    auto loadc = [&](int kc) {
        #pragma unroll
        for (int i = 0; i < 8; ++i) {
            const int v   = i * 256 + tid;
            const int row = v >> 4;
            const int col = (v & 15) << 2;
            px[i] = *reinterpret_cast<const float4*>(
                xs0 + (size_t)row * I_DIM + kc * KC + col);
            pw[i] = *reinterpret_cast<const float4*>(
                ws0 + (size_t)row * I_DIM + kc * KC + col);
        }
    };

    auto storec = [&](char* bb) {
        #pragma unroll
        for (int i = 0; i < 8; ++i) {
            const int v   = i * 256 + tid;
            const int row = v >> 4;
            const int col = (v & 15) << 2;
            const uint32_t off = (uint32_t)(row * 128 + col * 2);
            const uint32_t sw  = off ^ ((off >> 3) & 0x70);
            split_store2(bb, sw, px[i]);
            split_store2(bb + 2 * TILE_B, sw, pw[i]);
        }
    };

    auto mmac = [&](uint32_t bbu) {
        const int PA[3] = {0, 0, 1};
        const int PB[3] = {0, 1, 0};
        #pragma unroll
        for (int p = 0; p < 3; ++p) {
            const uint32_t At = bbu + PA[p] * TILE_B;
            const uint32_t Bt = bbu + (2 + PB[p]) * TILE_B;
            #pragma unroll
            for (int ks = 0; ks < 4; ++ks) {
                uint32_t a[2][4];
                #pragma unroll
                for (int mt = 0; mt < 2; ++mt) {
                    const int row = wm * 32 + mt * 16 + (lane & 15);
                    const uint32_t off = (uint32_t)(row * 128 + ks * 32 + ((lane >> 4) << 4));
                    const uint32_t ad  = At + (off ^ ((off >> 3) & 0x70));
                    LDSM4(a[mt][0], a[mt][1], a[mt][2], a[mt][3], ad);
                }
                #pragma unroll
                for (int nq = 0; nq < 4; ++nq) {
                    const int g = lane >> 3, r = lane & 7;
                    const int nrow = wn * 64 + nq * 16 + ((g >> 1) << 3) + r;
                    const uint32_t off = (uint32_t)(nrow * 128 + ks * 32 + ((g & 1) << 4));
                    const uint32_t ad  = Bt + (off ^ ((off >> 3) & 0x70));
                    uint32_t b0, b1, b2, b3;
                    LDSM4(b0, b1, b2, b3, ad);
                    MMA_OP(acc[0][2 * nq],     a[0], b0, b1);
                    MMA_OP(acc[1][2 * nq],     a[1], b0, b1);
                    MMA_OP(acc[0][2 * nq + 1], a[0], b2, b3);
                    MMA_OP(acc[1][2 * nq + 1], a[1], b2, b3);
                }
            }
        }
    };

    loadc(0);
    for (int kc = 0; kc < NKC; ++kc) {
        char*    bb  = sm + (kc & 1) * BUF_B;
        uint32_t bbu = sb + (kc & 1) * BUF_B;
        storec(bb);
        __syncthreads();
        if (kc + 1 < NKC) loadc(kc + 1);
        mmac(bbu);
    }

    {
        const int rbase = m0 + wm * 32 + (lane >> 2);
        const int nb    = n0 + wn * 64 + (lane & 3) * 2;
        #pragma unroll
        for (int nt = 0; nt < 8; ++nt) {
            const int n = nb + nt * 8;
            const float2 bv = *reinterpret_cast<const float2*>(bias + n);
            #pragma unroll
            for (int mt = 0; mt < 2; ++mt) {
                const int r0 = rbase + mt * 16;
                float2 o0, o1;
                o0.x = acc[mt][nt][0] + bv.x;
                o0.y = acc[mt][nt][1] + bv.y;
                o1.x = acc[mt][nt][2] + bv.x;
                o1.y = acc[mt][nt][3] + bv.y;
                *reinterpret_cast<float2*>(&g_cur[(size_t)r0 * O_DIM + n])       = o0;
                *reinterpret_cast<float2*>(&g_cur[(size_t)(r0 + 8) * O_DIM + n]) = o1;
            }
        }
    }
}

// ---------------------------------------------------------------------------
// Zero the flag counter (pure kernel node; capture-safe).
// ---------------------------------------------------------------------------
__global__ void snn_zero() { g_flag_cnt = 0; }

// ---------------------------------------------------------------------------
// Scan + ambiguity flagging (single aggregated atomic per flagging thread).
// ---------------------------------------------------------------------------
__global__ __launch_bounds__(256)
void snn_scan_flag(float* __restrict__ out) {
    const int lane4 = blockIdx.x * blockDim.x + threadIdx.x;
    const size_t base = (size_t)lane4 * 4;

    float4 mem = make_float4(0.f, 0.f, 0.f, 0.f);
    int fl0 = 0, fl1 = 0, fl2 = 0, fl3 = 0;

    #pragma unroll 5
    for (int t = 0; t < T_STEPS; ++t) {
        const size_t off = (size_t)t * BO + base;
        float4 c = *reinterpret_cast<const float4*>(&g_cur[off]);

        mem.x = BETA_F * mem.x + c.x;
        mem.y = BETA_F * mem.y + c.y;
        mem.z = BETA_F * mem.z + c.z;
        mem.w = BETA_F * mem.w + c.w;

        fl0 |= (fabsf(mem.x - THRESH_F) < DELTA_MEM);
        fl1 |= (fabsf(mem.y - THRESH_F) < DELTA_MEM);
        fl2 |= (fabsf(mem.z - THRESH_F) < DELTA_MEM);
        fl3 |= (fabsf(mem.w - THRESH_F) < DELTA_MEM);

        float4 spk;
        spk.x = (mem.x >= THRESH_F) ? 1.0f : 0.0f;
        spk.y = (mem.y >= THRESH_F) ? 1.0f : 0.0f;
        spk.z = (mem.z >= THRESH_F) ? 1.0f : 0.0f;
        spk.w = (mem.w >= THRESH_F) ? 1.0f : 0.0f;

        *reinterpret_cast<float4*>(&out[off]) = spk;

        mem.x -= spk.x * THRESH_F;
        mem.y -= spk.y * THRESH_F;
        mem.z -= spk.z * THRESH_F;
        mem.w -= spk.w * THRESH_F;
    }

    const int nf = fl0 + fl1 + fl2 + fl3;
    if (nf) {
        int pos = atomicAdd(&g_flag_cnt, nf);
        if (fl0) g_flag_list[pos++] = (int)base + 0;
        if (fl1) g_flag_list[pos++] = (int)base + 1;
        if (fl2) g_flag_list[pos++] = (int)base + 2;
        if (fl3) g_flag_list[pos++] = (int)base + 3;
    }
}

// ---------------------------------------------------------------------------
// Fixup A (v3): one block per batch b. Collect this b's flagged o's, then for
// each 32-t tile: stage X[t0..t0+31, b, :] into smem COALESCED (row stride
// 516 floats = 4*odd -> LDS.128 at the 4-cycle crossbar floor, 16B-aligned
// rows), then compute with warp = 4 neurons, lane = t. One smem x read
// serves 4 neurons; w rows are warp-broadcast LDGs (L1-resident).
// Each (t, neuron) keeps its own STRICT k-ascending fp32 fmaf chain
// (+bias at end) — the proven-exact repair arithmetic.
// ---------------------------------------------------------------------------
#define XROW_F 516                       // floats per staged row (pad 4)
#define FIX_SMEM (32 * XROW_F * 4)       // 66048 B

__global__ __launch_bounds__(256)
void snn_fix_cur(const float* __restrict__ X, const float* __restrict__ Wm,
                 const float* __restrict__ bias)
{
    extern __shared__ float xs[];        // [32][XROW_F]
    __shared__ unsigned short s_olist[O_DIM];
    __shared__ int s_cnt;

    const int b    = blockIdx.x;
    const int tid  = threadIdx.x;
    const int warp = tid >> 5;
    const int lane = tid & 31;

    if (tid == 0) s_cnt = 0;
    __syncthreads();

    const int total_flags = g_flag_cnt;
    for (int i = tid; i < total_flags; i += blockDim.x) {
        const int bo = g_flag_list[i];
        if ((bo >> 9) == b) {
            const int pos = atomicAdd(&s_cnt, 1);
            s_olist[pos] = (unsigned short)(bo & 511);
        }
    }
    __syncthreads();

    const int cnt = s_cnt;
    if (cnt == 0) return;

    for (int t0 = 0; t0 < T_STEPS; t0 += 32) {
        const int tl = (T_STEPS - t0 < 32) ? (T_STEPS - t0) : 32;

        // Stage x rows for t in [t0, t0+tl): coalesced float4 loads.
        for (int v = tid; v < tl * 128; v += 256) {
            const int row = v >> 7;          // 0..tl-1
            const int c4  = v & 127;         // float4 index in row
            const float4 xv = *reinterpret_cast<const float4*>(
                X + ((size_t)(t0 + row) * B_DIM + b) * I_DIM + c4 * 4);
            *reinterpret_cast<float4*>(&xs[row * XROW_F + c4 * 4]) = xv;
        }
        __syncthreads();

        const int t = t0 + lane;
        const bool tok = (t < T_STEPS);

        // Neuron rounds: 8 warps x 4 neurons = 32 neurons per round.
        for (int r0 = 0; r0 < cnt; r0 += 32) {
            const int nbase = r0 + warp * 4;

            int      o[4];
            const float4* wr[4];
            bool     ok[4];
            #pragma unroll
            for (int j = 0; j < 4; ++j) {
                const int ni = nbase + j;
                ok[j] = (ni < cnt);
                o[j]  = ok[j] ? (int)s_olist[ni] : (int)s_olist[0];
                wr[j] = reinterpret_cast<const float4*>(Wm + (size_t)o[j] * I_DIM);
            }

            if (tok) {
                float a0 = 0.f, a1 = 0.f, a2 = 0.f, a3 = 0.f;
                const float4* xr = reinterpret_cast<const float4*>(&xs[lane * XROW_F]);
                #pragma unroll 4
                for (int k4 = 0; k4 < I_DIM / 4; ++k4) {
                    const float4 xv = xr[k4];                 // smem, 4-cyc floor
                    const float4 w0 = __ldg(&wr[0][k4]);      // warp-broadcast
                    const float4 w1 = __ldg(&wr[1][k4]);
                    const float4 w2 = __ldg(&wr[2][k4]);
                    const float4 w3 = __ldg(&wr[3][k4]);
                    a0 = fmaf(xv.x, w0.x, a0); a0 = fmaf(xv.y, w0.y, a0);
                    a0 = fmaf(xv.z, w0.z, a0); a0 = fmaf(xv.w, w0.w, a0);
                    a1 = fmaf(xv.x, w1.x, a1); a1 = fmaf(xv.y, w1.y, a1);
                    a1 = fmaf(xv.z, w1.z, a1); a1 = fmaf(xv.w, w1.w, a1);
                    a2 = fmaf(xv.x, w2.x, a2); a2 = fmaf(xv.y, w2.y, a2);
                    a2 = fmaf(xv.z, w2.z, a2); a2 = fmaf(xv.w, w2.w, a2);
                    a3 = fmaf(xv.x, w3.x, a3); a3 = fmaf(xv.y, w3.y, a3);
                    a3 = fmaf(xv.z, w3.z, a3); a3 = fmaf(xv.w, w3.w, a3);
                }
                const size_t rowb = (size_t)t * BO + (size_t)b * O_DIM;
                if (ok[0]) g_cur[rowb + o[0]] = a0 + bias[o[0]];
                if (ok[1]) g_cur[rowb + o[1]] = a1 + bias[o[1]];
                if (ok[2]) g_cur[rowb + o[2]] = a2 + bias[o[2]];
                if (ok[3]) g_cur[rowb + o[3]] = a3 + bias[o[3]];
            }
        }
        __syncthreads();   // staging buffer reused next tile
    }
}

// ---------------------------------------------------------------------------
// Fixup B: re-scan flagged neurons and overwrite out.
// ---------------------------------------------------------------------------
__global__ __launch_bounds__(256)
void snn_fix_scan(float* __restrict__ out) {
    const int F = g_flag_cnt;
    const int stride = gridDim.x * blockDim.x;

    for (int fi = blockIdx.x * blockDim.x + threadIdx.x; fi < F; fi += stride) {
        const int bo = g_flag_list[fi];
        float mem = 0.0f;
        for (int t = 0; t < T_STEPS; ++t) {
            const float c = g_cur[(size_t)t * BO + bo];
            mem = BETA_F * mem + c;
            const float spk = (mem >= THRESH_F) ? 1.0f : 0.0f;
            out[(size_t)t * BO + bo] = spk;
            mem -= spk * THRESH_F;
        }
    }
}

// ---------------------------------------------------------------------------
extern "C" void kernel_launch(void* const* d_in, const int* in_sizes, int n_in,
                              void* d_out, int out_size) {
    const float* x    = (const float*)d_in[0]; // [T, B, I]
    const float* w    = (const float*)d_in[1]; // [O, I]
    const float* bias = (const float*)d_in[2]; // [O]
    float* out = (float*)d_out;                // [T, B, O]

    cudaFuncSetAttribute(snn_gemm_mma,
                         cudaFuncAttributeMaxDynamicSharedMemorySize, SMEM_ASK);
    cudaFuncSetAttribute(snn_fix_cur,
                         cudaFuncAttributeMaxDynamicSharedMemorySize, FIX_SMEM);

    snn_zero<<<1, 1>>>();

    dim3 grid(O_DIM / 128, M_DIM / 128);       // (4, 400), n fastest
    snn_gemm_mma<<<grid, 256, SMEM_ASK>>>(x, w, bias);

    snn_scan_flag<<<(BO / 4) / 256, 256>>>(out);

    snn_fix_cur<<<B_DIM, 256, FIX_SMEM>>>(x, w, bias);
    snn_fix_scan<<<64, 256>>>(out);
}

// round 13
// speedup vs baseline: 1.0727x; 1.0727x over previous
#include <cuda_runtime.h>
#include <cuda_bf16.h>
#include <cstdint>
#include <cstddef>

// Problem constants
#define T_STEPS 100
#define B_DIM   512
#define I_DIM   512
#define O_DIM   512
#define M_DIM   (T_STEPS * B_DIM)   // 51200
#define BO      (B_DIM * O_DIM)     // 262144

#define BETA_F   0.9f
#define THRESH_F 1.0f
#define DELTA_MEM 1.5e-4f           // flag margin: ~3.5x max |mem_tc - mem_seq|

// Scratch for input currents cur[T, B, O] (105 MB)
__device__ float g_cur[(size_t)T_STEPS * B_DIM * O_DIM];
// Per-batch buckets of flagged neuron o-indices
__device__ unsigned short g_bucket[B_DIM][O_DIM];   // 512 KB
__device__ int g_bcnt[B_DIM];

// ---------------------------------------------------------------------------
// bf16x2 split GEMM on legacy tensor cores — R10 interleaved structure
// (measured ~346us): all 8 warps alternate split/store and mma; double-
// buffered smem; gmem prefetch of chunk k+1 issued before mma of chunk k.
// 3 product GEMMs: (a1,b1), (a1,b2), (a2,b1); dropped term ~2^-18 rel.
// ---------------------------------------------------------------------------
#define KC        64
#define NKC       (I_DIM / KC)        // 8
#define TILE_B    (128 * 128)         // 16384 B
#define BUF_B     (4 * TILE_B)        // 65536 B: a1 a2 b1 b2
#define SMEM_ASK  (1024 + 2 * BUF_B)  // 132096 B

static __device__ __forceinline__ uint32_t smem_u32(const void* p) {
    uint32_t a;
    asm("{ .reg .u64 t; cvta.to.shared.u64 t, %1; cvt.u32.u64 %0, t; }"
        : "=r"(a) : "l"(p));
    return a;
}

#define LDSM4(r0, r1, r2, r3, addr) \
    asm volatile("ldmatrix.sync.aligned.m8n8.x4.shared.b16 {%0,%1,%2,%3}, [%4];" \
        : "=r"(r0), "=r"(r1), "=r"(r2), "=r"(r3) : "r"(addr))

#define MMA_OP(D, A, b0, b1) \
    asm volatile("mma.sync.aligned.m16n8k16.row.col.f32.bf16.bf16.f32 " \
        "{%0,%1,%2,%3}, {%4,%5,%6,%7}, {%8,%9}, {%0,%1,%2,%3};" \
        : "+f"((D)[0]), "+f"((D)[1]), "+f"((D)[2]), "+f"((D)[3]) \
        : "r"((A)[0]), "r"((A)[1]), "r"((A)[2]), "r"((A)[3]), "r"(b0), "r"(b1))

static __device__ __forceinline__ uint32_t pack2(__nv_bfloat16 lo, __nv_bfloat16 hi) {
    __nv_bfloat162 p = __halves2bfloat162(lo, hi);
    return *reinterpret_cast<uint32_t*>(&p);
}

static __device__ __forceinline__ void split_store2(char* tile0, uint32_t sw, float4 v) {
    float f0 = v.x, f1 = v.y, f2 = v.z, f3 = v.w;

    __nv_bfloat16 a0 = __float2bfloat16_rn(f0);
    __nv_bfloat16 a1 = __float2bfloat16_rn(f1);
    __nv_bfloat16 a2 = __float2bfloat16_rn(f2);
    __nv_bfloat16 a3 = __float2bfloat16_rn(f3);

    float r0 = f0 - __bfloat162float(a0);
    float r1 = f1 - __bfloat162float(a1);
    float r2 = f2 - __bfloat162float(a2);
    float r3 = f3 - __bfloat162float(a3);

    __nv_bfloat16 b0 = __float2bfloat16_rn(r0);
    __nv_bfloat16 b1 = __float2bfloat16_rn(r1);
    __nv_bfloat16 b2 = __float2bfloat16_rn(r2);
    __nv_bfloat16 b3 = __float2bfloat16_rn(r3);

    uint2 w1; w1.x = pack2(a0, a1); w1.y = pack2(a2, a3);
    uint2 w2; w2.x = pack2(b0, b1); w2.y = pack2(b2, b3);

    *reinterpret_cast<uint2*>(tile0 + sw)          = w1;
    *reinterpret_cast<uint2*>(tile0 + TILE_B + sw) = w2;
}

__global__ void __launch_bounds__(256)
snn_gemm_mma(const float* __restrict__ X, const float* __restrict__ Wm,
             const float* __restrict__ bias)
{
    extern __shared__ char smraw[];
    char* sm = (char*)((((uintptr_t)smraw) + 1023) & ~(uintptr_t)1023);
    const uint32_t sb = smem_u32(sm);

    const int tid  = threadIdx.x;
    const int warp = tid >> 5;
    const int lane = tid & 31;
    const int wm   = warp & 3;
    const int wn   = warp >> 2;

    const int n0 = blockIdx.x * 128;
    const int m0 = blockIdx.y * 128;

    const float* xs0 = X  + (size_t)m0 * I_DIM;
    const float* ws0 = Wm + (size_t)n0 * I_DIM;

    float acc[2][8][4] = {};
    float4 px[8], pw[8];

    auto loadc = [&](int kc) {
        #pragma unroll
        for (int i = 0; i < 8; ++i) {
            const int v   = i * 256 + tid;
            const int row = v >> 4;
            const int col = (v & 15) << 2;
            px[i] = *reinterpret_cast<const float4*>(
                xs0 + (size_t)row * I_DIM + kc * KC + col);
            pw[i] = *reinterpret_cast<const float4*>(
                ws0 + (size_t)row * I_DIM + kc * KC + col);
        }
    };

    auto storec = [&](char* bb) {
        #pragma unroll
        for (int i = 0; i < 8; ++i) {
            const int v   = i * 256 + tid;
            const int row = v >> 4;
            const int col = (v & 15) << 2;
            const uint32_t off = (uint32_t)(row * 128 + col * 2);
            const uint32_t sw  = off ^ ((off >> 3) & 0x70);
            split_store2(bb, sw, px[i]);
            split_store2(bb + 2 * TILE_B, sw, pw[i]);
        }
    };

    auto mmac = [&](uint32_t bbu) {
        const int PA[3] = {0, 0, 1};
        const int PB[3] = {0, 1, 0};
        #pragma unroll
        for (int p = 0; p < 3; ++p) {
            const uint32_t At = bbu + PA[p] * TILE_B;
            const uint32_t Bt = bbu + (2 + PB[p]) * TILE_B;
            #pragma unroll
            for (int ks = 0; ks < 4; ++ks) {
                uint32_t a[2][4];
                #pragma unroll
                for (int mt = 0; mt < 2; ++mt) {
                    const int row = wm * 32 + mt * 16 + (lane & 15);
                    const uint32_t off = (uint32_t)(row * 128 + ks * 32 + ((lane >> 4) << 4));
                    const uint32_t ad  = At + (off ^ ((off >> 3) & 0x70));
                    LDSM4(a[mt][0], a[mt][1], a[mt][2], a[mt][3], ad);
                }
                #pragma unroll
                for (int nq = 0; nq < 4; ++nq) {
                    const int g = lane >> 3, r = lane & 7;
                    const int nrow = wn * 64 + nq * 16 + ((g >> 1) << 3) + r;
                    const uint32_t off = (uint32_t)(nrow * 128 + ks * 32 + ((g & 1) << 4));
                    const uint32_t ad  = Bt + (off ^ ((off >> 3) & 0x70));
                    uint32_t b0, b1, b2, b3;
                    LDSM4(b0, b1, b2, b3, ad);
                    MMA_OP(acc[0][2 * nq],     a[0], b0, b1);
                    MMA_OP(acc[1][2 * nq],     a[1], b0, b1);
                    MMA_OP(acc[0][2 * nq + 1], a[0], b2, b3);
                    MMA_OP(acc[1][2 * nq + 1], a[1], b2, b3);
                }
            }
        }
    };

    loadc(0);
    for (int kc = 0; kc < NKC; ++kc) {
        char*    bb  = sm + (kc & 1) * BUF_B;
        uint32_t bbu = sb + (kc & 1) * BUF_B;
        storec(bb);
        __syncthreads();
        if (kc + 1 < NKC) loadc(kc + 1);
        mmac(bbu);
    }

    {
        const int rbase = m0 + wm * 32 + (lane >> 2);
        const int nb    = n0 + wn * 64 + (lane & 3) * 2;
        #pragma unroll
        for (int nt = 0; nt < 8; ++nt) {
            const int n = nb + nt * 8;
            const float2 bv = *reinterpret_cast<const float2*>(bias + n);
            #pragma unroll
            for (int mt = 0; mt < 2; ++mt) {
                const int r0 = rbase + mt * 16;
                float2 o0, o1;
                o0.x = acc[mt][nt][0] + bv.x;
                o0.y = acc[mt][nt][1] + bv.y;
                o1.x = acc[mt][nt][2] + bv.x;
                o1.y = acc[mt][nt][3] + bv.y;
                *reinterpret_cast<float2*>(&g_cur[(size_t)r0 * O_DIM + n])       = o0;
                *reinterpret_cast<float2*>(&g_cur[(size_t)(r0 + 8) * O_DIM + n]) = o1;
            }
        }
    }
}

// ---------------------------------------------------------------------------
// Zero per-batch bucket counters (pure kernel node; capture-safe).
// ---------------------------------------------------------------------------
__global__ void snn_zero() {
    const int i = blockIdx.x * blockDim.x + threadIdx.x;
    if (i < B_DIM) g_bcnt[i] = 0;
}

// ---------------------------------------------------------------------------
// Scan + ambiguity flagging: flagged neurons pushed into per-batch buckets.
// A thread's 4 lanes share one b (base = lane4*4, O=512 divides 4).
// ---------------------------------------------------------------------------
__global__ __launch_bounds__(256)
void snn_scan_flag(float* __restrict__ out) {
    const int lane4 = blockIdx.x * blockDim.x + threadIdx.x;
    const size_t base = (size_t)lane4 * 4;
    const int b  = (int)(base >> 9);
    const int o0 = (int)(base & 511);

    float4 mem = make_float4(0.f, 0.f, 0.f, 0.f);
    int fl0 = 0, fl1 = 0, fl2 = 0, fl3 = 0;

    #pragma unroll 5
    for (int t = 0; t < T_STEPS; ++t) {
        const size_t off = (size_t)t * BO + base;
        float4 c = *reinterpret_cast<const float4*>(&g_cur[off]);

        mem.x = BETA_F * mem.x + c.x;
        mem.y = BETA_F * mem.y + c.y;
        mem.z = BETA_F * mem.z + c.z;
        mem.w = BETA_F * mem.w + c.w;

        fl0 |= (fabsf(mem.x - THRESH_F) < DELTA_MEM);
        fl1 |= (fabsf(mem.y - THRESH_F) < DELTA_MEM);
        fl2 |= (fabsf(mem.z - THRESH_F) < DELTA_MEM);
        fl3 |= (fabsf(mem.w - THRESH_F) < DELTA_MEM);

        float4 spk;
        spk.x = (mem.x >= THRESH_F) ? 1.0f : 0.0f;
        spk.y = (mem.y >= THRESH_F) ? 1.0f : 0.0f;
        spk.z = (mem.z >= THRESH_F) ? 1.0f : 0.0f;
        spk.w = (mem.w >= THRESH_F) ? 1.0f : 0.0f;

        *reinterpret_cast<float4*>(&out[off]) = spk;

        mem.x -= spk.x * THRESH_F;
        mem.y -= spk.y * THRESH_F;
        mem.z -= spk.z * THRESH_F;
        mem.w -= spk.w * THRESH_F;
    }

    const int nf = fl0 + fl1 + fl2 + fl3;
    if (nf) {
        int pos = atomicAdd(&g_bcnt[b], nf);   // one atomic per flagging thread
        if (fl0) g_bucket[b][pos++] = (unsigned short)(o0 + 0);
        if (fl1) g_bucket[b][pos++] = (unsigned short)(o0 + 1);
        if (fl2) g_bucket[b][pos++] = (unsigned short)(o0 + 2);
        if (fl3) g_bucket[b][pos++] = (unsigned short)(o0 + 3);
    }
}

// ---------------------------------------------------------------------------
// Fixup A (v4): block per batch b; warp = 4 same-b neurons x 8 timesteps.
// Lane (j, ti): j = lane>>3 selects neuron, ti = lane&7 selects t.
// x row shared by 4 lanes (same t,b): 8 wavefronts per LDG.128.
// w row shared by 8 lanes (same o):   4 wavefronts per LDG.128.
// Each (t, neuron) pair keeps its own STRICT k-ascending fp32 fmaf chain
// (+bias at end) — identical arithmetic to the proven repair.
// ---------------------------------------------------------------------------
#define NT_OCT 13          // ceil(100/8)

__global__ __launch_bounds__(256)
void snn_fix_cur(const float* __restrict__ X, const float* __restrict__ Wm,
                 const float* __restrict__ bias)
{
    const int b    = blockIdx.x;
    const int warp = threadIdx.x >> 5;
    const int lane = threadIdx.x & 31;

    const int cnt = g_bcnt[b];
    if (cnt == 0) return;

    const int nquads = (cnt + 3) >> 2;
    const int ntasks = nquads * NT_OCT;

    const int j  = lane >> 3;      // neuron slot in quad
    const int ti = lane & 7;       // t within octet

    for (int wt = warp; wt < ntasks; wt += 8) {
        const int qi = wt / NT_OCT;
        const int tg = wt - qi * NT_OCT;

        const int ni = qi * 4 + j;
        const bool ok = (ni < cnt);
        const int o  = (int)g_bucket[b][ok ? ni : 0];

        const int t   = tg * 8 + ti;
        const bool tok = ok && (t < T_STEPS);
        const int tt  = (t < T_STEPS) ? t : (T_STEPS - 1);   // clamp for safe loads

        const float4* xr = reinterpret_cast<const float4*>(
            X + ((size_t)tt * B_DIM + b) * I_DIM);
        const float4* wr = reinterpret_cast<const float4*>(
            Wm + (size_t)o * I_DIM);

        float acc = 0.0f;
        #pragma unroll 4
        for (int k4 = 0; k4 < I_DIM / 4; ++k4) {
            const float4 xv = __ldg(&xr[k4]);   // 4-lane shared
            const float4 wv = __ldg(&wr[k4]);   // 8-lane shared
            acc = fmaf(xv.x, wv.x, acc);
            acc = fmaf(xv.y, wv.y, acc);
            acc = fmaf(xv.z, wv.z, acc);
            acc = fmaf(xv.w, wv.w, acc);
        }
        if (tok)
            g_cur[(size_t)t * BO + (size_t)b * O_DIM + o] = acc + bias[o];
    }
}

// ---------------------------------------------------------------------------
// Fixup B: re-scan flagged neurons (bucketed) and overwrite out.
// ---------------------------------------------------------------------------
__global__ __launch_bounds__(256)
void snn_fix_scan(float* __restrict__ out) {
    const int b   = blockIdx.x;
    const int cnt = g_bcnt[b];

    for (int i = threadIdx.x; i < cnt; i += blockDim.x) {
        const int o  = (int)g_bucket[b][i];
        const size_t bo = (size_t)b * O_DIM + o;
        float mem = 0.0f;
        for (int t = 0; t < T_STEPS; ++t) {
            const float c = g_cur[(size_t)t * BO + bo];
            mem = BETA_F * mem + c;
            const float spk = (mem >= THRESH_F) ? 1.0f : 0.0f;
            out[(size_t)t * BO + bo] = spk;
            mem -= spk * THRESH_F;
        }
    }
}

// ---------------------------------------------------------------------------
extern "C" void kernel_launch(void* const* d_in, const int* in_sizes, int n_in,
                              void* d_out, int out_size) {
    const float* x    = (const float*)d_in[0]; // [T, B, I]
    const float* w    = (const float*)d_in[1]; // [O, I]
    const float* bias = (const float*)d_in[2]; // [O]
    float* out = (float*)d_out;                // [T, B, O]

    cudaFuncSetAttribute(snn_gemm_mma,
                         cudaFuncAttributeMaxDynamicSharedMemorySize, SMEM_ASK);

    snn_zero<<<2, 256>>>();

    dim3 grid(O_DIM / 128, M_DIM / 128);       // (4, 400), n fastest
    snn_gemm_mma<<<grid, 256, SMEM_ASK>>>(x, w, bias);

    snn_scan_flag<<<(BO / 4) / 256, 256>>>(out);

    snn_fix_cur<<<B_DIM, 256>>>(x, w, bias);   // block per b, warp = 4n x 8t
    snn_fix_scan<<<B_DIM, 256>>>(out);
}

// round 16
// speedup vs baseline: 1.2996x; 1.2115x over previous
#include <cuda_runtime.h>
#include <cuda_bf16.h>
#include <cstdint>
#include <cstddef>

// Problem constants
#define T_STEPS 100
#define B_DIM   512
#define I_DIM   512
#define O_DIM   512
#define M_DIM   (T_STEPS * B_DIM)   // 51200
#define BO      (B_DIM * O_DIM)     // 262144

#define BETA_F   0.9f
#define THRESH_F 1.0f
#define DELTA_MEM 1.5e-4f           // flag margin: ~3.5x max |mem_tc - mem_seq|

// Scratch for input currents cur[T, B, O] (105 MB)
__device__ float g_cur[(size_t)T_STEPS * B_DIM * O_DIM];
// Per-batch buckets of flagged neuron o-indices
__device__ unsigned short g_bucket[B_DIM][O_DIM];   // 512 KB
__device__ int g_bcnt[B_DIM];

// ---------------------------------------------------------------------------
// bf16x2 split GEMM on legacy tensor cores — R10 interleaved structure
// (measured ~346us): all 8 warps alternate split/store and mma; double-
// buffered smem; gmem prefetch of chunk k+1 issued before mma of chunk k.
// 3 product GEMMs: (a1,b1), (a1,b2), (a2,b1); dropped term ~2^-18 rel.
// ---------------------------------------------------------------------------
#define KC        64
#define NKC       (I_DIM / KC)        // 8
#define TILE_B    (128 * 128)         // 16384 B
#define BUF_B     (4 * TILE_B)        // 65536 B: a1 a2 b1 b2
#define SMEM_ASK  (1024 + 2 * BUF_B)  // 132096 B

static __device__ __forceinline__ uint32_t smem_u32(const void* p) {
    uint32_t a;
    asm("{ .reg .u64 t; cvta.to.shared.u64 t, %1; cvt.u32.u64 %0, t; }"
        : "=r"(a) : "l"(p));
    return a;
}

#define LDSM4(r0, r1, r2, r3, addr) \
    asm volatile("ldmatrix.sync.aligned.m8n8.x4.shared.b16 {%0,%1,%2,%3}, [%4];" \
        : "=r"(r0), "=r"(r1), "=r"(r2), "=r"(r3) : "r"(addr))

#define MMA_OP(D, A, b0, b1) \
    asm volatile("mma.sync.aligned.m16n8k16.row.col.f32.bf16.bf16.f32 " \
        "{%0,%1,%2,%3}, {%4,%5,%6,%7}, {%8,%9}, {%0,%1,%2,%3};" \
        : "+f"((D)[0]), "+f"((D)[1]), "+f"((D)[2]), "+f"((D)[3]) \
        : "r"((A)[0]), "r"((A)[1]), "r"((A)[2]), "r"((A)[3]), "r"(b0), "r"(b1))

static __device__ __forceinline__ uint32_t pack2(__nv_bfloat16 lo, __nv_bfloat16 hi) {
    __nv_bfloat162 p = __halves2bfloat162(lo, hi);
    return *reinterpret_cast<uint32_t*>(&p);
}

static __device__ __forceinline__ void split_store2(char* tile0, uint32_t sw, float4 v) {
    float f0 = v.x, f1 = v.y, f2 = v.z, f3 = v.w;

    __nv_bfloat16 a0 = __float2bfloat16_rn(f0);
    __nv_bfloat16 a1 = __float2bfloat16_rn(f1);
    __nv_bfloat16 a2 = __float2bfloat16_rn(f2);
    __nv_bfloat16 a3 = __float2bfloat16_rn(f3);

    float r0 = f0 - __bfloat162float(a0);
    float r1 = f1 - __bfloat162float(a1);
    float r2 = f2 - __bfloat162float(a2);
    float r3 = f3 - __bfloat162float(a3);

    __nv_bfloat16 b0 = __float2bfloat16_rn(r0);
    __nv_bfloat16 b1 = __float2bfloat16_rn(r1);
    __nv_bfloat16 b2 = __float2bfloat16_rn(r2);
    __nv_bfloat16 b3 = __float2bfloat16_rn(r3);

    uint2 w1; w1.x = pack2(a0, a1); w1.y = pack2(a2, a3);
    uint2 w2; w2.x = pack2(b0, b1); w2.y = pack2(b2, b3);

    *reinterpret_cast<uint2*>(tile0 + sw)          = w1;
    *reinterpret_cast<uint2*>(tile0 + TILE_B + sw) = w2;
}

__global__ void __launch_bounds__(256)
snn_gemm_mma(const float* __restrict__ X, const float* __restrict__ Wm,
             const float* __restrict__ bias)
{
    extern __shared__ char smraw[];
    char* sm = (char*)((((uintptr_t)smraw) + 1023) & ~(uintptr_t)1023);
    const uint32_t sb = smem_u32(sm);

    const int tid  = threadIdx.x;
    const int warp = tid >> 5;
    const int lane = tid & 31;
    const int wm   = warp & 3;
    const int wn   = warp >> 2;

    const int n0 = blockIdx.x * 128;
    const int m0 = blockIdx.y * 128;

    const float* xs0 = X  + (size_t)m0 * I_DIM;
    const float* ws0 = Wm + (size_t)n0 * I_DIM;

    float acc[2][8][4] = {};
    float4 px[8], pw[8];

    auto loadc = [&](int kc) {
        #pragma unroll
        for (int i = 0; i < 8; ++i) {
            const int v   = i * 256 + tid;
            const int row = v >> 4;
            const int col = (v & 15) << 2;
            px[i] = *reinterpret_cast<const float4*>(
                xs0 + (size_t)row * I_DIM + kc * KC + col);
            pw[i] = *reinterpret_cast<const float4*>(
                ws0 + (size_t)row * I_DIM + kc * KC + col);
        }
    };

    auto storec = [&](char* bb) {
        #pragma unroll
        for (int i = 0; i < 8; ++i) {
            const int v   = i * 256 + tid;
            const int row = v >> 4;
            const int col = (v & 15) << 2;
            const uint32_t off = (uint32_t)(row * 128 + col * 2);
            const uint32_t sw  = off ^ ((off >> 3) & 0x70);
            split_store2(bb, sw, px[i]);
            split_store2(bb + 2 * TILE_B, sw, pw[i]);
        }
    };

    auto mmac = [&](uint32_t bbu) {
        const int PA[3] = {0, 0, 1};
        const int PB[3] = {0, 1, 0};
        #pragma unroll
        for (int p = 0; p < 3; ++p) {
            const uint32_t At = bbu + PA[p] * TILE_B;
            const uint32_t Bt = bbu + (2 + PB[p]) * TILE_B;
            #pragma unroll
            for (int ks = 0; ks < 4; ++ks) {
                uint32_t a[2][4];
                #pragma unroll
                for (int mt = 0; mt < 2; ++mt) {
                    const int row = wm * 32 + mt * 16 + (lane & 15);
                    const uint32_t off = (uint32_t)(row * 128 + ks * 32 + ((lane >> 4) << 4));
                    const uint32_t ad  = At + (off ^ ((off >> 3) & 0x70));
                    LDSM4(a[mt][0], a[mt][1], a[mt][2], a[mt][3], ad);
                }
                #pragma unroll
                for (int nq = 0; nq < 4; ++nq) {
                    const int g = lane >> 3, r = lane & 7;
                    const int nrow = wn * 64 + nq * 16 + ((g >> 1) << 3) + r;
                    const uint32_t off = (uint32_t)(nrow * 128 + ks * 32 + ((g & 1) << 4));
                    const uint32_t ad  = Bt + (off ^ ((off >> 3) & 0x70));
                    uint32_t b0, b1, b2, b3;
                    LDSM4(b0, b1, b2, b3, ad);
                    MMA_OP(acc[0][2 * nq],     a[0], b0, b1);
                    MMA_OP(acc[1][2 * nq],     a[1], b0, b1);
                    MMA_OP(acc[0][2 * nq + 1], a[0], b2, b3);
                    MMA_OP(acc[1][2 * nq + 1], a[1], b2, b3);
                }
            }
        }
    };

    loadc(0);
    for (int kc = 0; kc < NKC; ++kc) {
        char*    bb  = sm + (kc & 1) * BUF_B;
        uint32_t bbu = sb + (kc & 1) * BUF_B;
        storec(bb);
        __syncthreads();
        if (kc + 1 < NKC) loadc(kc + 1);
        mmac(bbu);
    }

    {
        const int rbase = m0 + wm * 32 + (lane >> 2);
        const int nb    = n0 + wn * 64 + (lane & 3) * 2;
        #pragma unroll
        for (int nt = 0; nt < 8; ++nt) {
            const int n = nb + nt * 8;
            const float2 bv = *reinterpret_cast<const float2*>(bias + n);
            #pragma unroll
            for (int mt = 0; mt < 2; ++mt) {
                const int r0 = rbase + mt * 16;
                float2 o0, o1;
                o0.x = acc[mt][nt][0] + bv.x;
                o0.y = acc[mt][nt][1] + bv.y;
                o1.x = acc[mt][nt][2] + bv.x;
                o1.y = acc[mt][nt][3] + bv.y;
                *reinterpret_cast<float2*>(&g_cur[(size_t)r0 * O_DIM + n])       = o0;
                *reinterpret_cast<float2*>(&g_cur[(size_t)(r0 + 8) * O_DIM + n]) = o1;
            }
        }
    }
}

// ---------------------------------------------------------------------------
// Zero per-batch bucket counters (pure kernel node; capture-safe).
// ---------------------------------------------------------------------------
__global__ void snn_zero() {
    const int i = blockIdx.x * blockDim.x + threadIdx.x;
    if (i < B_DIM) g_bcnt[i] = 0;
}

// ---------------------------------------------------------------------------
// Scan + ambiguity flagging: flagged neurons pushed into per-batch buckets.
// ---------------------------------------------------------------------------
__global__ __launch_bounds__(256)
void snn_scan_flag(float* __restrict__ out) {
    const int lane4 = blockIdx.x * blockDim.x + threadIdx.x;
    const size_t base = (size_t)lane4 * 4;
    const int b  = (int)(base >> 9);
    const int o0 = (int)(base & 511);

    float4 mem = make_float4(0.f, 0.f, 0.f, 0.f);
    int fl0 = 0, fl1 = 0, fl2 = 0, fl3 = 0;

    #pragma unroll 5
    for (int t = 0; t < T_STEPS; ++t) {
        const size_t off = (size_t)t * BO + base;
        float4 c = *reinterpret_cast<const float4*>(&g_cur[off]);

        mem.x = BETA_F * mem.x + c.x;
        mem.y = BETA_F * mem.y + c.y;
        mem.z = BETA_F * mem.z + c.z;
        mem.w = BETA_F * mem.w + c.w;

        fl0 |= (fabsf(mem.x - THRESH_F) < DELTA_MEM);
        fl1 |= (fabsf(mem.y - THRESH_F) < DELTA_MEM);
        fl2 |= (fabsf(mem.z - THRESH_F) < DELTA_MEM);
        fl3 |= (fabsf(mem.w - THRESH_F) < DELTA_MEM);

        float4 spk;
        spk.x = (mem.x >= THRESH_F) ? 1.0f : 0.0f;
        spk.y = (mem.y >= THRESH_F) ? 1.0f : 0.0f;
        spk.z = (mem.z >= THRESH_F) ? 1.0f : 0.0f;
        spk.w = (mem.w >= THRESH_F) ? 1.0f : 0.0f;

        *reinterpret_cast<float4*>(&out[off]) = spk;

        mem.x -= spk.x * THRESH_F;
        mem.y -= spk.y * THRESH_F;
        mem.z -= spk.z * THRESH_F;
        mem.w -= spk.w * THRESH_F;
    }

    const int nf = fl0 + fl1 + fl2 + fl3;
    if (nf) {
        int pos = atomicAdd(&g_bcnt[b], nf);
        if (fl0) g_bucket[b][pos++] = (unsigned short)(o0 + 0);
        if (fl1) g_bucket[b][pos++] = (unsigned short)(o0 + 1);
        if (fl2) g_bucket[b][pos++] = (unsigned short)(o0 + 2);
        if (fl3) g_bucket[b][pos++] = (unsigned short)(o0 + 3);
    }
}

// ---------------------------------------------------------------------------
// Fixup A (v5): grid (b, 4 t-groups); lane = t within group; warps stride
// over same-b neuron QUADS. Each lane keeps 4 independent strict k-ascending
// fp32 fmaf chains (identical arithmetic to the proven repair): one x
// LDG.128 per k4 serves all 4 neurons (R12's efficient loop) while the
// (b, t-group) grid supplies R11-scale parallelism without smem staging.
// ---------------------------------------------------------------------------
__global__ __launch_bounds__(256)
void snn_fix_cur(const float* __restrict__ X, const float* __restrict__ Wm,
                 const float* __restrict__ bias)
{
    const int b    = blockIdx.x;
    const int tg   = blockIdx.y;          // 0..3
    const int warp = threadIdx.x >> 5;
    const int lane = threadIdx.x & 31;

    const int cnt = g_bcnt[b];
    if (cnt == 0) return;

    const int t   = tg * 32 + lane;
    const bool tok = (t < T_STEPS);
    const int tt  = tok ? t : 0;          // clamp for safe loads

    const float4* xr = reinterpret_cast<const float4*>(
        X + ((size_t)tt * B_DIM + b) * I_DIM);

    const int nquads = (cnt + 3) >> 2;

    for (int qi = warp; qi < nquads; qi += 8) {
        int      o[4];
        const float4* wr[4];
        bool     ok[4];
        #pragma unroll
        for (int j = 0; j < 4; ++j) {
            const int ni = qi * 4 + j;
            ok[j] = (ni < cnt);
            o[j]  = (int)g_bucket[b][ok[j] ? ni : 0];
            wr[j] = reinterpret_cast<const float4*>(Wm + (size_t)o[j] * I_DIM);
        }

        float a0 = 0.f, a1 = 0.f, a2 = 0.f, a3 = 0.f;
        #pragma unroll 4
        for (int k4 = 0; k4 < I_DIM / 4; ++k4) {
            const float4 xv = __ldg(&xr[k4]);      // one x load serves 4 neurons
            const float4 w0 = __ldg(&wr[0][k4]);   // warp-broadcast
            const float4 w1 = __ldg(&wr[1][k4]);
            const float4 w2 = __ldg(&wr[2][k4]);
            const float4 w3 = __ldg(&wr[3][k4]);
            a0 = fmaf(xv.x, w0.x, a0); a0 = fmaf(xv.y, w0.y, a0);
            a0 = fmaf(xv.z, w0.z, a0); a0 = fmaf(xv.w, w0.w, a0);
            a1 = fmaf(xv.x, w1.x, a1); a1 = fmaf(xv.y, w1.y, a1);
            a1 = fmaf(xv.z, w1.z, a1); a1 = fmaf(xv.w, w1.w, a1);
            a2 = fmaf(xv.x, w2.x, a2); a2 = fmaf(xv.y, w2.y, a2);
            a2 = fmaf(xv.z, w2.z, a2); a2 = fmaf(xv.w, w2.w, a2);
            a3 = fmaf(xv.x, w3.x, a3); a3 = fmaf(xv.y, w3.y, a3);
            a3 = fmaf(xv.z, w3.z, a3); a3 = fmaf(xv.w, w3.w, a3);
        }

        if (tok) {
            const size_t rowb = (size_t)t * BO + (size_t)b * O_DIM;
            if (ok[0]) g_cur[rowb + o[0]] = a0 + bias[o[0]];
            if (ok[1]) g_cur[rowb + o[1]] = a1 + bias[o[1]];
            if (ok[2]) g_cur[rowb + o[2]] = a2 + bias[o[2]];
            if (ok[3]) g_cur[rowb + o[3]] = a3 + bias[o[3]];
        }
    }
}

// ---------------------------------------------------------------------------
// Fixup B: re-scan flagged neurons (bucketed) and overwrite out.
// ---------------------------------------------------------------------------
__global__ __launch_bounds__(256)
void snn_fix_scan(float* __restrict__ out) {
    const int b   = blockIdx.x;
    const int cnt = g_bcnt[b];

    for (int i = threadIdx.x; i < cnt; i += blockDim.x) {
        const int o  = (int)g_bucket[b][i];
        const size_t bo = (size_t)b * O_DIM + o;
        float mem = 0.0f;
        for (int t = 0; t < T_STEPS; ++t) {
            const float c = g_cur[(size_t)t * BO + bo];
            mem = BETA_F * mem + c;
            const float spk = (mem >= THRESH_F) ? 1.0f : 0.0f;
            out[(size_t)t * BO + bo] = spk;
            mem -= spk * THRESH_F;
        }
    }
}

// ---------------------------------------------------------------------------
extern "C" void kernel_launch(void* const* d_in, const int* in_sizes, int n_in,
                              void* d_out, int out_size) {
    const float* x    = (const float*)d_in[0]; // [T, B, I]
    const float* w    = (const float*)d_in[1]; // [O, I]
    const float* bias = (const float*)d_in[2]; // [O]
    float* out = (float*)d_out;                // [T, B, O]

    cudaFuncSetAttribute(snn_gemm_mma,
                         cudaFuncAttributeMaxDynamicSharedMemorySize, SMEM_ASK);

    snn_zero<<<2, 256>>>();

    dim3 grid(O_DIM / 128, M_DIM / 128);       // (4, 400), n fastest
    snn_gemm_mma<<<grid, 256, SMEM_ASK>>>(x, w, bias);

    snn_scan_flag<<<(BO / 4) / 256, 256>>>(out);

    dim3 fgrid(B_DIM, 4);                      // (b, t-group)
    snn_fix_cur<<<fgrid, 256>>>(x, w, bias);
    snn_fix_scan<<<B_DIM, 256>>>(out);
}